// round 9
// baseline (speedup 1.0000x reference)
#include <cuda_runtime.h>
#include <cstdint>

// ---------------------------------------------------------------------------
// QLoRA 4-bit: y = x @ (dequant(W)^T + 2 * W_a @ W_b)
//   1) build_weff: NF4 dequant + LoRA fold -> fp32 W_eff (tf32-pre-rounded)
//   2) qgemm: TF32 m16n8k8, CTA 256x128, 8 warps, warp tile 64x64
//      (smem bytes/MAC 1.5x lower than r8's 32x64), 3-stage cp.async (.cg),
//      ldmatrix-for-tf32 fragment feed.
// ---------------------------------------------------------------------------

namespace {
constexpr int D_IN  = 4096;
constexpr int D_OUT = 4096;
constexpr int M_TOK = 8192;
constexpr int RNK   = 16;

constexpr int BM = 256, BN = 128, BK = 16;   // BK floats = 64 B/row
constexpr int KP = 20;                        // row pitch floats (80 B)
constexpr int NT = D_IN / BK;                 // 256 k-tiles
constexpr int NTHREADS = 256;
constexpr int STAGES = 3;
constexpr int A_ST = BM * KP * 4;             // 20480 B
constexpr int B_ST = BN * KP * 4;             // 10240 B
constexpr int STAGE_BYTES = A_ST + B_ST;      // 30720 B
constexpr int SMEM_DYN = STAGES * STAGE_BYTES;  // 92160 B
}

// scratch (allocation-free rule: __device__ global)
__device__ __align__(16) float d_Weff[(size_t)D_OUT * D_IN];   // 64 MB

__device__ const float g_nf4[16] = {
    -1.0f, -0.6961928009986877f, -0.5250730514526367f, -0.39491748809814453f,
    -0.28444138169288635f, -0.18477343022823334f, -0.09105003625154495f, 0.0f,
    0.07958029955625534f, 0.16093020141124725f, 0.24611230194568634f,
    0.33791524171829224f, 0.44070982933044434f, 0.5626170039176941f,
    0.7229568362236023f, 1.0f};

__device__ __forceinline__ unsigned f2tf32(float x) {
    unsigned r;
    asm("cvt.rna.tf32.f32 %0, %1;" : "=r"(r) : "f"(x));
    return r;
}
__device__ __forceinline__ uint32_t smem_u32(const void* p) {
    uint32_t a;
    asm("{ .reg .u64 t; cvta.to.shared.u64 t, %1; cvt.u32.u64 %0, t; }" : "=r"(a) : "l"(p));
    return a;
}
__device__ __forceinline__ void cp_async16(uint32_t saddr, const void* gaddr) {
    asm volatile("cp.async.cg.shared.global [%0], [%1], 16;\n" :: "r"(saddr), "l"(gaddr));
}
__device__ __forceinline__ void ldsm_x4(uint32_t& r0, uint32_t& r1, uint32_t& r2,
                                        uint32_t& r3, uint32_t addr) {
    asm volatile("ldmatrix.sync.aligned.m8n8.x4.shared.b16 {%0,%1,%2,%3}, [%4];"
                 : "=r"(r0), "=r"(r1), "=r"(r2), "=r"(r3) : "r"(addr));
}
__device__ __forceinline__ void mma_tf32(float* d, const unsigned* a, const unsigned* b) {
    asm volatile(
        "mma.sync.aligned.m16n8k8.row.col.f32.tf32.tf32.f32 "
        "{%0,%1,%2,%3}, {%4,%5,%6,%7}, {%8,%9}, {%0,%1,%2,%3};\n"
        : "+f"(d[0]), "+f"(d[1]), "+f"(d[2]), "+f"(d[3])
        : "r"(a[0]), "r"(a[1]), "r"(a[2]), "r"(a[3]), "r"(b[0]), "r"(b[1]));
}

// ---------------------------------------------------------------------------
// W_eff[n][k] = nf4[codes[n][k]]*absmax[n][k/64] + 2*sum_r Wa[k][r]*Wb[r][n]
__global__ void build_weff_kernel(const int4* __restrict__ codes4,
                                  const float* __restrict__ absmax,
                                  const float* __restrict__ Wa,
                                  const float* __restrict__ Wb) {
    __shared__ float lut[16];
    const int n = blockIdx.x;
    if (threadIdx.x < 16) lut[threadIdx.x] = g_nf4[threadIdx.x];
    float wb[RNK];
#pragma unroll
    for (int r = 0; r < RNK; r++) wb[r] = __ldg(&Wb[r * D_OUT + n]);
    __syncthreads();

    const int4*  crow = codes4 + (size_t)n * (D_IN / 4);
    const float* am   = absmax + (size_t)n * (D_IN / 64);
    float4*      orow = reinterpret_cast<float4*>(d_Weff + (size_t)n * D_IN);

    for (int g = threadIdx.x; g < D_IN / 4; g += blockDim.x) {
        const int4 c = crow[g];
        const float s = am[g >> 4];
        const int k0 = g * 4;
        float v[4] = {lut[c.x & 15] * s, lut[c.y & 15] * s,
                      lut[c.z & 15] * s, lut[c.w & 15] * s};
#pragma unroll
        for (int j = 0; j < 4; j++) {
            const float4* wa = reinterpret_cast<const float4*>(Wa + (size_t)(k0 + j) * RNK);
            float4 a0 = wa[0], a1 = wa[1], a2 = wa[2], a3 = wa[3];
            float l = a0.x * wb[0]  + a0.y * wb[1]  + a0.z * wb[2]  + a0.w * wb[3]
                    + a1.x * wb[4]  + a1.y * wb[5]  + a1.z * wb[6]  + a1.w * wb[7]
                    + a2.x * wb[8]  + a2.y * wb[9]  + a2.z * wb[10] + a2.w * wb[11]
                    + a3.x * wb[12] + a3.y * wb[13] + a3.z * wb[14] + a3.w * wb[15];
            v[j] += 2.0f * l;                   // SCALE = 2
        }
        orow[g] = make_float4(__uint_as_float(f2tf32(v[0])),
                              __uint_as_float(f2tf32(v[1])),
                              __uint_as_float(f2tf32(v[2])),
                              __uint_as_float(f2tf32(v[3])));
    }
}

// ---------------------------------------------------------------------------
// TF32 GEMM: C = x * W_eff^T.  CTA 256x128, warps 4M x 2N, warp tile 64x64.
__global__ __launch_bounds__(NTHREADS)
void qgemm(const float* __restrict__ A, float* __restrict__ C) {
    extern __shared__ __align__(16) char smem[];
    const uint32_t sb = smem_u32(smem);

    const int tid  = threadIdx.x, lane = tid & 31, warp = tid >> 5;
    const int warpM = warp & 3;          // 4 slabs of 64 rows
    const int warpN = warp >> 2;         // 2 slabs of 64 cols
    const int gid = lane >> 2, tig = lane & 3;

    const int mBase = blockIdx.y * BM;
    const int nBase = blockIdx.x * BN;

    const int ldRow = tid >> 2;          // 0..63
    const int ldCol = (tid & 3) << 2;    // float offset 0,4,8,12

    const float* Agp = A      + (size_t)(mBase + ldRow) * D_IN + ldCol;
    const float* Bgp = d_Weff + (size_t)(nBase + ldRow) * D_IN + ldCol;

    // ldmatrix lane-address components
    const int lm_m = lane >> 3, lm_j = lane & 7;
    const uint32_t aRowOff = ((lm_m & 1) * 8 + lm_j) * (KP * 4);
    const uint32_t aColOff = (lm_m >> 1) * 16;       // bytes
    const uint32_t bRowOff = ((lm_m >> 1) * 8 + lm_j) * (KP * 4);
    const uint32_t bColOff = (lm_m & 1) * 16;        // bytes

    auto load_stage = [&](int s, int kt) {
        const uint32_t As = sb + s * STAGE_BYTES;
        const uint32_t Bs = As + A_ST;
        const int k0 = kt * BK;
#pragma unroll
        for (int h = 0; h < 4; h++) {    // A: 256 rows
            const uint32_t so = (ldRow + 64 * h) * (KP * 4) + ldCol * 4;
            cp_async16(As + so, Agp + (size_t)(64 * h) * D_IN + k0);
        }
#pragma unroll
        for (int h = 0; h < 2; h++) {    // B: 128 rows
            const uint32_t so = (ldRow + 64 * h) * (KP * 4) + ldCol * 4;
            cp_async16(Bs + so, Bgp + (size_t)(64 * h) * D_IN + k0);
        }
    };

    float acc[4][8][4];
#pragma unroll
    for (int i = 0; i < 4; i++)
#pragma unroll
        for (int j = 0; j < 8; j++)
#pragma unroll
            for (int v = 0; v < 4; v++) acc[i][j][v] = 0.f;

    // prologue: stages 0,1
#pragma unroll
    for (int s = 0; s < 2; s++) {
        load_stage(s, s);
        asm volatile("cp.async.commit_group;\n");
    }

    for (int kt = 0; kt < NT; kt++) {
        asm volatile("cp.async.wait_group 1;\n");
        __syncthreads();
        const int s = kt % STAGES;
        const uint32_t Ab = sb + s * STAGE_BYTES;
        const uint32_t Bb = Ab + A_ST;

#pragma unroll
        for (int kk = 0; kk < BK; kk += 8) {
            unsigned a[4][4];
#pragma unroll
            for (int mi = 0; mi < 4; mi++) {
                uint32_t r0, r1, r2, r3;
                const uint32_t addr = Ab + (warpM * 64 + mi * 16) * (KP * 4)
                                    + aRowOff + kk * 4 + aColOff;
                ldsm_x4(r0, r1, r2, r3, addr);
                a[mi][0] = f2tf32(__uint_as_float(r0));
                a[mi][1] = f2tf32(__uint_as_float(r1));
                a[mi][2] = f2tf32(__uint_as_float(r2));
                a[mi][3] = f2tf32(__uint_as_float(r3));
            }
            unsigned b[8][2];
#pragma unroll
            for (int np = 0; np < 4; np++) {
                uint32_t r0, r1, r2, r3;
                const uint32_t addr = Bb + (warpN * 64 + np * 16) * (KP * 4)
                                    + bRowOff + kk * 4 + bColOff;
                ldsm_x4(r0, r1, r2, r3, addr);       // W_eff pre-rounded
                b[2 * np][0] = r0;  b[2 * np][1] = r1;
                b[2 * np + 1][0] = r2;  b[2 * np + 1][1] = r3;
            }
#pragma unroll
            for (int mi = 0; mi < 4; mi++)
#pragma unroll
                for (int ni = 0; ni < 8; ni++)
                    mma_tf32(acc[mi][ni], a[mi], b[ni]);
        }
        __syncthreads();

        if (kt + 2 < NT)
            load_stage((kt + 2) % STAGES, kt + 2);
        asm volatile("cp.async.commit_group;\n");
    }

    // epilogue: float2 stores
#pragma unroll
    for (int mi = 0; mi < 4; mi++) {
        const int row0 = mBase + warpM * 64 + mi * 16 + gid;
#pragma unroll
        for (int ni = 0; ni < 8; ni++) {
            const int col = nBase + warpN * 64 + ni * 8 + tig * 2;
            *reinterpret_cast<float2*>(C + (size_t)row0 * D_OUT + col) =
                make_float2(acc[mi][ni][0], acc[mi][ni][1]);
            *reinterpret_cast<float2*>(C + (size_t)(row0 + 8) * D_OUT + col) =
                make_float2(acc[mi][ni][2], acc[mi][ni][3]);
        }
    }
}

// ---------------------------------------------------------------------------
extern "C" void kernel_launch(void* const* d_in, const int* in_sizes, int n_in,
                              void* d_out, int out_size) {
    const float* x      = (const float*)d_in[0];
    const int*   codes  = (const int*)  d_in[1];
    const float* absmax = (const float*)d_in[2];
    const float* Wa     = (const float*)d_in[3];
    const float* Wb     = (const float*)d_in[4];
    float* out = (float*)d_out;

    cudaFuncSetAttribute(qgemm, cudaFuncAttributeMaxDynamicSharedMemorySize, SMEM_DYN);

    build_weff_kernel<<<D_OUT, 256>>>((const int4*)codes, absmax, Wa, Wb);

    dim3 grid(D_OUT / BN, M_TOK / BM);   // (32, 32), n-fast for W_eff L2 reuse
    qgemm<<<grid, NTHREADS, SMEM_DYN>>>(x, out);
}

// round 11
// speedup vs baseline: 1.0203x; 1.0203x over previous
#include <cuda_runtime.h>
#include <cstdint>

// ---------------------------------------------------------------------------
// QLoRA 4-bit: y = x @ (dequant(W)^T + 2 * W_a @ W_b)
//   1) build_weff: NF4 dequant + LoRA fold -> fp32 W_eff (tf32-pre-rounded)
//   2) qgemm: TF32 m16n8k8. CTA 128x128 with 128 threads (4 warps, 2Mx2N,
//      warp tile 64x64 => low smem B/MAC like r9) AND 2 CTAs/SM (restores
//      latency hiding that r9 lost). True depth-3 cp.async pipeline.
// ---------------------------------------------------------------------------

namespace {
constexpr int D_IN  = 4096;
constexpr int D_OUT = 4096;
constexpr int M_TOK = 8192;
constexpr int RNK   = 16;

constexpr int BM = 128, BN = 128, BK = 16;   // BK floats = 64 B/row
constexpr int KP = 20;                        // row pitch floats (80 B)
constexpr int NT = D_IN / BK;                 // 256 k-tiles
constexpr int NTHREADS = 128;
constexpr int STAGES = 3;
constexpr int A_ST = BM * KP * 4;             // 10240 B
constexpr int B_ST = BN * KP * 4;             // 10240 B
constexpr int STAGE_BYTES = A_ST + B_ST;      // 20480 B
constexpr int SMEM_DYN = STAGES * STAGE_BYTES;  // 61440 B -> 2 CTAs/SM
}

// scratch (allocation-free rule: __device__ global)
__device__ __align__(16) float d_Weff[(size_t)D_OUT * D_IN];   // 64 MB

__device__ const float g_nf4[16] = {
    -1.0f, -0.6961928009986877f, -0.5250730514526367f, -0.39491748809814453f,
    -0.28444138169288635f, -0.18477343022823334f, -0.09105003625154495f, 0.0f,
    0.07958029955625534f, 0.16093020141124725f, 0.24611230194568634f,
    0.33791524171829224f, 0.44070982933044434f, 0.5626170039176941f,
    0.7229568362236023f, 1.0f};

__device__ __forceinline__ unsigned f2tf32(float x) {
    unsigned r;
    asm("cvt.rna.tf32.f32 %0, %1;" : "=r"(r) : "f"(x));
    return r;
}
__device__ __forceinline__ uint32_t smem_u32(const void* p) {
    uint32_t a;
    asm("{ .reg .u64 t; cvta.to.shared.u64 t, %1; cvt.u32.u64 %0, t; }" : "=r"(a) : "l"(p));
    return a;
}
__device__ __forceinline__ void cp_async16(uint32_t saddr, const void* gaddr) {
    asm volatile("cp.async.cg.shared.global [%0], [%1], 16;\n" :: "r"(saddr), "l"(gaddr));
}
__device__ __forceinline__ void ldsm_x4(uint32_t& r0, uint32_t& r1, uint32_t& r2,
                                        uint32_t& r3, uint32_t addr) {
    asm volatile("ldmatrix.sync.aligned.m8n8.x4.shared.b16 {%0,%1,%2,%3}, [%4];"
                 : "=r"(r0), "=r"(r1), "=r"(r2), "=r"(r3) : "r"(addr));
}
__device__ __forceinline__ void mma_tf32(float* d, const unsigned* a, const unsigned* b) {
    asm volatile(
        "mma.sync.aligned.m16n8k8.row.col.f32.tf32.tf32.f32 "
        "{%0,%1,%2,%3}, {%4,%5,%6,%7}, {%8,%9}, {%0,%1,%2,%3};\n"
        : "+f"(d[0]), "+f"(d[1]), "+f"(d[2]), "+f"(d[3])
        : "r"(a[0]), "r"(a[1]), "r"(a[2]), "r"(a[3]), "r"(b[0]), "r"(b[1]));
}

// ---------------------------------------------------------------------------
// W_eff[n][k] = nf4[codes[n][k]]*absmax[n][k/64] + 2*sum_r Wa[k][r]*Wb[r][n]
__global__ void build_weff_kernel(const int4* __restrict__ codes4,
                                  const float* __restrict__ absmax,
                                  const float* __restrict__ Wa,
                                  const float* __restrict__ Wb) {
    __shared__ float lut[16];
    const int n = blockIdx.x;
    if (threadIdx.x < 16) lut[threadIdx.x] = g_nf4[threadIdx.x];
    float wb[RNK];
#pragma unroll
    for (int r = 0; r < RNK; r++) wb[r] = __ldg(&Wb[r * D_OUT + n]);
    __syncthreads();

    const int4*  crow = codes4 + (size_t)n * (D_IN / 4);
    const float* am   = absmax + (size_t)n * (D_IN / 64);
    float4*      orow = reinterpret_cast<float4*>(d_Weff + (size_t)n * D_IN);

    for (int g = threadIdx.x; g < D_IN / 4; g += blockDim.x) {
        const int4 c = crow[g];
        const float s = am[g >> 4];
        const int k0 = g * 4;
        float v[4] = {lut[c.x & 15] * s, lut[c.y & 15] * s,
                      lut[c.z & 15] * s, lut[c.w & 15] * s};
#pragma unroll
        for (int j = 0; j < 4; j++) {
            const float4* wa = reinterpret_cast<const float4*>(Wa + (size_t)(k0 + j) * RNK);
            float4 a0 = wa[0], a1 = wa[1], a2 = wa[2], a3 = wa[3];
            float l = a0.x * wb[0]  + a0.y * wb[1]  + a0.z * wb[2]  + a0.w * wb[3]
                    + a1.x * wb[4]  + a1.y * wb[5]  + a1.z * wb[6]  + a1.w * wb[7]
                    + a2.x * wb[8]  + a2.y * wb[9]  + a2.z * wb[10] + a2.w * wb[11]
                    + a3.x * wb[12] + a3.y * wb[13] + a3.z * wb[14] + a3.w * wb[15];
            v[j] += 2.0f * l;                   // SCALE = 2
        }
        orow[g] = make_float4(__uint_as_float(f2tf32(v[0])),
                              __uint_as_float(f2tf32(v[1])),
                              __uint_as_float(f2tf32(v[2])),
                              __uint_as_float(f2tf32(v[3])));
    }
}

// ---------------------------------------------------------------------------
// TF32 GEMM: C = x * W_eff^T. CTA 128x128, 128 thr, 4 warps 2Mx2N (64x64 each).
__global__ __launch_bounds__(NTHREADS)
void qgemm(const float* __restrict__ A, float* __restrict__ C) {
    extern __shared__ __align__(16) char smem[];
    const uint32_t sb = smem_u32(smem);

    const int tid  = threadIdx.x, lane = tid & 31, warp = tid >> 5;
    const int warpM = warp & 1;          // 2 slabs of 64 rows
    const int warpN = warp >> 1;         // 2 slabs of 64 cols
    const int gid = lane >> 2, tig = lane & 3;

    const int mBase = blockIdx.y * BM;
    const int nBase = blockIdx.x * BN;

    const int ldRow = tid >> 2;          // 0..31
    const int ldCol = (tid & 3) << 2;    // float offset 0,4,8,12

    const float* Agp = A      + (size_t)(mBase + ldRow) * D_IN + ldCol;
    const float* Bgp = d_Weff + (size_t)(nBase + ldRow) * D_IN + ldCol;

    // ldmatrix lane-address components
    const int lm_m = lane >> 3, lm_j = lane & 7;
    const uint32_t aRowOff = ((lm_m & 1) * 8 + lm_j) * (KP * 4);
    const uint32_t aColOff = (lm_m >> 1) * 16;       // bytes
    const uint32_t bRowOff = ((lm_m >> 1) * 8 + lm_j) * (KP * 4);
    const uint32_t bColOff = (lm_m & 1) * 16;        // bytes

    auto load_stage = [&](int s, int kt) {
        const uint32_t As = sb + s * STAGE_BYTES;
        const uint32_t Bs = As + A_ST;
        const int k0 = kt * BK;
#pragma unroll
        for (int h = 0; h < 4; h++) {    // A: 128 rows, 32 rows per pass
            const uint32_t so = (ldRow + 32 * h) * (KP * 4) + ldCol * 4;
            cp_async16(As + so, Agp + (size_t)(32 * h) * D_IN + k0);
        }
#pragma unroll
        for (int h = 0; h < 4; h++) {    // B: 128 rows
            const uint32_t so = (ldRow + 32 * h) * (KP * 4) + ldCol * 4;
            cp_async16(Bs + so, Bgp + (size_t)(32 * h) * D_IN + k0);
        }
    };

    float acc[4][8][4];
#pragma unroll
    for (int i = 0; i < 4; i++)
#pragma unroll
        for (int j = 0; j < 8; j++)
#pragma unroll
            for (int v = 0; v < 4; v++) acc[i][j][v] = 0.f;

    // prologue: fill all 3 stages
#pragma unroll
    for (int s = 0; s < STAGES; s++) {
        load_stage(s, s);
        asm volatile("cp.async.commit_group;\n");
    }

    for (int kt = 0; kt < NT; kt++) {
        asm volatile("cp.async.wait_group %0;\n" :: "n"(STAGES - 1));
        __syncthreads();
        const int s = kt % STAGES;
        const uint32_t Ab = sb + s * STAGE_BYTES;
        const uint32_t Bb = Ab + A_ST;

#pragma unroll
        for (int kk = 0; kk < BK; kk += 8) {
            unsigned a[4][4];
#pragma unroll
            for (int mi = 0; mi < 4; mi++) {
                uint32_t r0, r1, r2, r3;
                const uint32_t addr = Ab + (warpM * 64 + mi * 16) * (KP * 4)
                                    + aRowOff + kk * 4 + aColOff;
                ldsm_x4(r0, r1, r2, r3, addr);
                a[mi][0] = f2tf32(__uint_as_float(r0));
                a[mi][1] = f2tf32(__uint_as_float(r1));
                a[mi][2] = f2tf32(__uint_as_float(r2));
                a[mi][3] = f2tf32(__uint_as_float(r3));
            }
            unsigned b[8][2];
#pragma unroll
            for (int np = 0; np < 4; np++) {
                uint32_t r0, r1, r2, r3;
                const uint32_t addr = Bb + (warpN * 64 + np * 16) * (KP * 4)
                                    + bRowOff + kk * 4 + bColOff;
                ldsm_x4(r0, r1, r2, r3, addr);       // W_eff pre-rounded
                b[2 * np][0] = r0;  b[2 * np][1] = r1;
                b[2 * np + 1][0] = r2;  b[2 * np + 1][1] = r3;
            }
#pragma unroll
            for (int mi = 0; mi < 4; mi++)
#pragma unroll
                for (int ni = 0; ni < 8; ni++)
                    mma_tf32(acc[mi][ni], a[mi], b[ni]);
        }
        __syncthreads();

        if (kt + STAGES < NT)
            load_stage(s, kt + STAGES);   // reuse the slot just consumed
        asm volatile("cp.async.commit_group;\n");
    }

    // epilogue: float2 stores
#pragma unroll
    for (int mi = 0; mi < 4; mi++) {
        const int row0 = mBase + warpM * 64 + mi * 16 + gid;
#pragma unroll
        for (int ni = 0; ni < 8; ni++) {
            const int col = nBase + warpN * 64 + ni * 8 + tig * 2;
            *reinterpret_cast<float2*>(C + (size_t)row0 * D_OUT + col) =
                make_float2(acc[mi][ni][0], acc[mi][ni][1]);
            *reinterpret_cast<float2*>(C + (size_t)(row0 + 8) * D_OUT + col) =
                make_float2(acc[mi][ni][2], acc[mi][ni][3]);
        }
    }
}

// ---------------------------------------------------------------------------
extern "C" void kernel_launch(void* const* d_in, const int* in_sizes, int n_in,
                              void* d_out, int out_size) {
    const float* x      = (const float*)d_in[0];
    const int*   codes  = (const int*)  d_in[1];
    const float* absmax = (const float*)d_in[2];
    const float* Wa     = (const float*)d_in[3];
    const float* Wb     = (const float*)d_in[4];
    float* out = (float*)d_out;

    cudaFuncSetAttribute(qgemm, cudaFuncAttributeMaxDynamicSharedMemorySize, SMEM_DYN);

    build_weff_kernel<<<D_OUT, 256>>>((const int4*)codes, absmax, Wa, Wb);

    dim3 grid(D_OUT / BN, M_TOK / BM);   // (32, 64), n-fast for W_eff L2 reuse
    qgemm<<<grid, NTHREADS, SMEM_DYN>>>(x, out);
}

// round 16
// speedup vs baseline: 1.2199x; 1.1956x over previous
#include <cuda_runtime.h>
#include <cstdint>

// ---------------------------------------------------------------------------
// QLoRA 4-bit: y = x @ (dequant(W)^T + 2 * W_a @ W_b)
//   1) build_weff: NF4 dequant + LoRA fold -> fp32 W_eff (tf32-pre-rounded)
//   2) qgemm: TF32 m16n8k8. CTA 128x128, 128 thr (4 warps 2Mx2N, 64x64 warp
//      tiles), 2 CTAs/SM, BK=32, 3-stage cp.async pipeline PLUS per-warp
//      fragment double-buffering (prefetch LDSM/cvt of k-step ks+1 under the
//      mmas of ks) -- attacks the flat tensor=50%/issue=21% ceiling that
//      persisted across r8/r9/r11 regardless of L1/occupancy.
// ---------------------------------------------------------------------------

namespace {
constexpr int D_IN  = 4096;
constexpr int D_OUT = 4096;
constexpr int M_TOK = 8192;
constexpr int RNK   = 16;

constexpr int BM = 128, BN = 128, BK = 32;   // BK floats = 128 B/row
constexpr int KP = 36;                        // row pitch floats (144 B)
constexpr int NT = D_IN / BK;                 // 128 k-tiles
constexpr int NTHREADS = 128;
constexpr int STAGES = 3;
constexpr int A_ST = BM * KP * 4;             // 18432 B
constexpr int B_ST = BN * KP * 4;             // 18432 B
constexpr int STAGE_BYTES = A_ST + B_ST;      // 36864 B
constexpr int SMEM_DYN = STAGES * STAGE_BYTES;  // 110592 B -> 2 CTAs/SM
}

// scratch (allocation-free rule: __device__ global)
__device__ __align__(16) float d_Weff[(size_t)D_OUT * D_IN];   // 64 MB

__device__ const float g_nf4[16] = {
    -1.0f, -0.6961928009986877f, -0.5250730514526367f, -0.39491748809814453f,
    -0.28444138169288635f, -0.18477343022823334f, -0.09105003625154495f, 0.0f,
    0.07958029955625534f, 0.16093020141124725f, 0.24611230194568634f,
    0.33791524171829224f, 0.44070982933044434f, 0.5626170039176941f,
    0.7229568362236023f, 1.0f};

__device__ __forceinline__ unsigned f2tf32(float x) {
    unsigned r;
    asm("cvt.rna.tf32.f32 %0, %1;" : "=r"(r) : "f"(x));
    return r;
}
__device__ __forceinline__ uint32_t smem_u32(const void* p) {
    uint32_t a;
    asm("{ .reg .u64 t; cvta.to.shared.u64 t, %1; cvt.u32.u64 %0, t; }" : "=r"(a) : "l"(p));
    return a;
}
__device__ __forceinline__ void cp_async16(uint32_t saddr, const void* gaddr) {
    asm volatile("cp.async.cg.shared.global [%0], [%1], 16;\n" :: "r"(saddr), "l"(gaddr));
}
__device__ __forceinline__ void ldsm_x4(uint32_t& r0, uint32_t& r1, uint32_t& r2,
                                        uint32_t& r3, uint32_t addr) {
    asm volatile("ldmatrix.sync.aligned.m8n8.x4.shared.b16 {%0,%1,%2,%3}, [%4];"
                 : "=r"(r0), "=r"(r1), "=r"(r2), "=r"(r3) : "r"(addr));
}
__device__ __forceinline__ void mma_tf32(float* d, const unsigned* a, const unsigned* b) {
    asm volatile(
        "mma.sync.aligned.m16n8k8.row.col.f32.tf32.tf32.f32 "
        "{%0,%1,%2,%3}, {%4,%5,%6,%7}, {%8,%9}, {%0,%1,%2,%3};\n"
        : "+f"(d[0]), "+f"(d[1]), "+f"(d[2]), "+f"(d[3])
        : "r"(a[0]), "r"(a[1]), "r"(a[2]), "r"(a[3]), "r"(b[0]), "r"(b[1]));
}

// ---------------------------------------------------------------------------
// W_eff[n][k] = nf4[codes[n][k]]*absmax[n][k/64] + 2*sum_r Wa[k][r]*Wb[r][n]
__global__ void build_weff_kernel(const int4* __restrict__ codes4,
                                  const float* __restrict__ absmax,
                                  const float* __restrict__ Wa,
                                  const float* __restrict__ Wb) {
    __shared__ float lut[16];
    const int n = blockIdx.x;
    if (threadIdx.x < 16) lut[threadIdx.x] = g_nf4[threadIdx.x];
    float wb[RNK];
#pragma unroll
    for (int r = 0; r < RNK; r++) wb[r] = __ldg(&Wb[r * D_OUT + n]);
    __syncthreads();

    const int4*  crow = codes4 + (size_t)n * (D_IN / 4);
    const float* am   = absmax + (size_t)n * (D_IN / 64);
    float4*      orow = reinterpret_cast<float4*>(d_Weff + (size_t)n * D_IN);

    for (int g = threadIdx.x; g < D_IN / 4; g += blockDim.x) {
        const int4 c = crow[g];
        const float s = am[g >> 4];
        const int k0 = g * 4;
        float v[4] = {lut[c.x & 15] * s, lut[c.y & 15] * s,
                      lut[c.z & 15] * s, lut[c.w & 15] * s};
#pragma unroll
        for (int j = 0; j < 4; j++) {
            const float4* wa = reinterpret_cast<const float4*>(Wa + (size_t)(k0 + j) * RNK);
            float4 a0 = wa[0], a1 = wa[1], a2 = wa[2], a3 = wa[3];
            float l = a0.x * wb[0]  + a0.y * wb[1]  + a0.z * wb[2]  + a0.w * wb[3]
                    + a1.x * wb[4]  + a1.y * wb[5]  + a1.z * wb[6]  + a1.w * wb[7]
                    + a2.x * wb[8]  + a2.y * wb[9]  + a2.z * wb[10] + a2.w * wb[11]
                    + a3.x * wb[12] + a3.y * wb[13] + a3.z * wb[14] + a3.w * wb[15];
            v[j] += 2.0f * l;                   // SCALE = 2
        }
        orow[g] = make_float4(__uint_as_float(f2tf32(v[0])),
                              __uint_as_float(f2tf32(v[1])),
                              __uint_as_float(f2tf32(v[2])),
                              __uint_as_float(f2tf32(v[3])));
    }
}

// ---------------------------------------------------------------------------
__global__ __launch_bounds__(NTHREADS, 2)
void qgemm(const float* __restrict__ A, float* __restrict__ C) {
    extern __shared__ __align__(16) char smem[];
    const uint32_t sb = smem_u32(smem);

    const int tid  = threadIdx.x, lane = tid & 31, warp = tid >> 5;
    const int warpM = warp & 1;          // 2 slabs of 64 rows
    const int warpN = warp >> 1;         // 2 slabs of 64 cols
    const int gid = lane >> 2, tig = lane & 3;

    const int mBase = blockIdx.y * BM;
    const int nBase = blockIdx.x * BN;

    const float* Agp = A      + (size_t)mBase * D_IN;
    const float* Bgp = d_Weff + (size_t)nBase * D_IN;

    // ldmatrix lane-address components
    const int lm_m = lane >> 3, lm_j = lane & 7;
    const uint32_t aRowOff = ((lm_m & 1) * 8 + lm_j) * (KP * 4);
    const uint32_t aColOff = (lm_m >> 1) * 16;       // bytes
    const uint32_t bRowOff = ((lm_m >> 1) * 8 + lm_j) * (KP * 4);
    const uint32_t bColOff = (lm_m & 1) * 16;        // bytes

    // cp.async map: 128 rows x 128B = 1024 chunks per operand; 8 per thread
    auto load_stage = [&](int s, int kt) {
        const uint32_t As = sb + s * STAGE_BYTES;
        const uint32_t Bs = As + A_ST;
        const char* Ag = (const char*)Agp + (size_t)kt * 128;
        const char* Bg = (const char*)Bgp + (size_t)kt * 128;
#pragma unroll
        for (int h = 0; h < 8; h++) {
            const int idx = tid + h * 128;
            const int row = idx >> 3;
            const uint32_t seg = (idx & 7) << 4;
            cp_async16(As + row * (KP * 4) + seg, Ag + (size_t)row * (D_IN * 4) + seg);
        }
#pragma unroll
        for (int h = 0; h < 8; h++) {
            const int idx = tid + h * 128;
            const int row = idx >> 3;
            const uint32_t seg = (idx & 7) << 4;
            cp_async16(Bs + row * (KP * 4) + seg, Bg + (size_t)row * (D_IN * 4) + seg);
        }
    };

    float acc[4][8][4];
#pragma unroll
    for (int i = 0; i < 4; i++)
#pragma unroll
        for (int j = 0; j < 8; j++)
#pragma unroll
            for (int v = 0; v < 4; v++) acc[i][j][v] = 0.f;

    // double-buffered fragments
    unsigned afr[2][4][4], bfr[2][8][2];

    auto frag_load = [&](int buf, uint32_t Ab, uint32_t Bb, int kk) {
#pragma unroll
        for (int mi = 0; mi < 4; mi++) {
            uint32_t r0, r1, r2, r3;
            const uint32_t addr = Ab + (warpM * 64 + mi * 16) * (KP * 4)
                                + aRowOff + kk * 4 + aColOff;
            ldsm_x4(r0, r1, r2, r3, addr);
            afr[buf][mi][0] = f2tf32(__uint_as_float(r0));
            afr[buf][mi][1] = f2tf32(__uint_as_float(r1));
            afr[buf][mi][2] = f2tf32(__uint_as_float(r2));
            afr[buf][mi][3] = f2tf32(__uint_as_float(r3));
        }
#pragma unroll
        for (int np = 0; np < 4; np++) {
            uint32_t r0, r1, r2, r3;
            const uint32_t addr = Bb + (warpN * 64 + np * 16) * (KP * 4)
                                + bRowOff + kk * 4 + bColOff;
            ldsm_x4(r0, r1, r2, r3, addr);           // W_eff pre-rounded
            bfr[buf][2 * np][0] = r0;  bfr[buf][2 * np][1] = r1;
            bfr[buf][2 * np + 1][0] = r2;  bfr[buf][2 * np + 1][1] = r3;
        }
    };

    // prologue: fill all 3 smem stages
#pragma unroll
    for (int s = 0; s < STAGES; s++) {
        load_stage(s, s);
        asm volatile("cp.async.commit_group;\n");
    }

    for (int kt = 0; kt < NT; kt++) {
        asm volatile("cp.async.wait_group %0;\n" :: "n"(STAGES - 1));
        __syncthreads();
        const int s = kt % STAGES;
        const uint32_t Ab = sb + s * STAGE_BYTES;
        const uint32_t Bb = Ab + A_ST;

        frag_load(0, Ab, Bb, 0);
#pragma unroll
        for (int ks = 0; ks < 4; ks++) {             // 4 k8-steps of BK=32
            const int cur = ks & 1;
            if (ks < 3) frag_load(cur ^ 1, Ab, Bb, (ks + 1) * 8);
#pragma unroll
            for (int mi = 0; mi < 4; mi++)
#pragma unroll
                for (int ni = 0; ni < 8; ni++)
                    mma_tf32(acc[mi][ni], afr[cur][mi], bfr[cur][ni]);
        }
        __syncthreads();

        if (kt + STAGES < NT)
            load_stage(s, kt + STAGES);              // refill the consumed slot
        asm volatile("cp.async.commit_group;\n");
    }

    // epilogue: float2 stores
#pragma unroll
    for (int mi = 0; mi < 4; mi++) {
        const int row0 = mBase + warpM * 64 + mi * 16 + gid;
#pragma unroll
        for (int ni = 0; ni < 8; ni++) {
            const int col = nBase + warpN * 64 + ni * 8 + tig * 2;
            *reinterpret_cast<float2*>(C + (size_t)row0 * D_OUT + col) =
                make_float2(acc[mi][ni][0], acc[mi][ni][1]);
            *reinterpret_cast<float2*>(C + (size_t)(row0 + 8) * D_OUT + col) =
                make_float2(acc[mi][ni][2], acc[mi][ni][3]);
        }
    }
}

// ---------------------------------------------------------------------------
extern "C" void kernel_launch(void* const* d_in, const int* in_sizes, int n_in,
                              void* d_out, int out_size) {
    const float* x      = (const float*)d_in[0];
    const int*   codes  = (const int*)  d_in[1];
    const float* absmax = (const float*)d_in[2];
    const float* Wa     = (const float*)d_in[3];
    const float* Wb     = (const float*)d_in[4];
    float* out = (float*)d_out;

    cudaFuncSetAttribute(qgemm, cudaFuncAttributeMaxDynamicSharedMemorySize, SMEM_DYN);

    build_weff_kernel<<<D_OUT, 256>>>((const int4*)codes, absmax, Wa, Wb);

    dim3 grid(D_OUT / BN, M_TOK / BM);   // (32, 64), n-fast for W_eff L2 reuse
    qgemm<<<grid, NTHREADS, SMEM_DYN>>>(x, out);
}

// round 17
// speedup vs baseline: 1.4617x; 1.1982x over previous
#include <cuda_runtime.h>
#include <cstdint>

// ---------------------------------------------------------------------------
// QLoRA 4-bit: y = x @ (dequant(W)^T + 2 * W_a @ W_b)
//   1) build_weff: NF4 dequant + LoRA fold -> fp32 W_eff (tf32-pre-rounded)
//   2) qgemm: TF32 m16n8k8, CTA 128x128 (4 warps, 64x64 warp tiles), BK=32,
//      fragment double-buffering (r16 win) PLUS:
//        - XOR-swizzled 128B smem rows (no padding): stage 32KB, 3 stages =
//          96KB -> genuinely 2 CTAs/SM (r16 was stuck at 1 via 110.6KB)
//        - single-barrier pipeline: wait_group -> sync -> refill (kt-1)%3 ->
//          compute (second per-tile __syncthreads eliminated)
// ---------------------------------------------------------------------------

namespace {
constexpr int D_IN  = 4096;
constexpr int D_OUT = 4096;
constexpr int M_TOK = 8192;
constexpr int RNK   = 16;

constexpr int BM = 128, BN = 128, BK = 32;     // BK floats = 128 B/row
constexpr int NT = D_IN / BK;                   // 128 k-tiles
constexpr int NTHREADS = 128;
constexpr int STAGES = 3;
constexpr int A_ST = BM * 128;                  // 16384 B (128B rows, swizzled)
constexpr int B_ST = BN * 128;                  // 16384 B
constexpr int STAGE_BYTES = A_ST + B_ST;        // 32768 B
constexpr int SMEM_DYN = STAGES * STAGE_BYTES;  // 98304 B -> 2 CTAs/SM
}

// scratch (allocation-free rule: __device__ global)
__device__ __align__(16) float d_Weff[(size_t)D_OUT * D_IN];   // 64 MB

__device__ const float g_nf4[16] = {
    -1.0f, -0.6961928009986877f, -0.5250730514526367f, -0.39491748809814453f,
    -0.28444138169288635f, -0.18477343022823334f, -0.09105003625154495f, 0.0f,
    0.07958029955625534f, 0.16093020141124725f, 0.24611230194568634f,
    0.33791524171829224f, 0.44070982933044434f, 0.5626170039176941f,
    0.7229568362236023f, 1.0f};

__device__ __forceinline__ unsigned f2tf32(float x) {
    unsigned r;
    asm("cvt.rna.tf32.f32 %0, %1;" : "=r"(r) : "f"(x));
    return r;
}
__device__ __forceinline__ uint32_t smem_u32(const void* p) {
    uint32_t a;
    asm("{ .reg .u64 t; cvta.to.shared.u64 t, %1; cvt.u32.u64 %0, t; }" : "=r"(a) : "l"(p));
    return a;
}
__device__ __forceinline__ void cp_async16(uint32_t saddr, const void* gaddr) {
    asm volatile("cp.async.cg.shared.global [%0], [%1], 16;\n" :: "r"(saddr), "l"(gaddr));
}
__device__ __forceinline__ void ldsm_x4(uint32_t& r0, uint32_t& r1, uint32_t& r2,
                                        uint32_t& r3, uint32_t addr) {
    asm volatile("ldmatrix.sync.aligned.m8n8.x4.shared.b16 {%0,%1,%2,%3}, [%4];"
                 : "=r"(r0), "=r"(r1), "=r"(r2), "=r"(r3) : "r"(addr));
}
__device__ __forceinline__ void mma_tf32(float* d, const unsigned* a, const unsigned* b) {
    asm volatile(
        "mma.sync.aligned.m16n8k8.row.col.f32.tf32.tf32.f32 "
        "{%0,%1,%2,%3}, {%4,%5,%6,%7}, {%8,%9}, {%0,%1,%2,%3};\n"
        : "+f"(d[0]), "+f"(d[1]), "+f"(d[2]), "+f"(d[3])
        : "r"(a[0]), "r"(a[1]), "r"(a[2]), "r"(a[3]), "r"(b[0]), "r"(b[1]));
}

// ---------------------------------------------------------------------------
// W_eff[n][k] = nf4[codes[n][k]]*absmax[n][k/64] + 2*sum_r Wa[k][r]*Wb[r][n]
__global__ void build_weff_kernel(const int4* __restrict__ codes4,
                                  const float* __restrict__ absmax,
                                  const float* __restrict__ Wa,
                                  const float* __restrict__ Wb) {
    __shared__ float lut[16];
    const int n = blockIdx.x;
    if (threadIdx.x < 16) lut[threadIdx.x] = g_nf4[threadIdx.x];
    float wb[RNK];
#pragma unroll
    for (int r = 0; r < RNK; r++) wb[r] = __ldg(&Wb[r * D_OUT + n]);
    __syncthreads();

    const int4*  crow = codes4 + (size_t)n * (D_IN / 4);
    const float* am   = absmax + (size_t)n * (D_IN / 64);
    float4*      orow = reinterpret_cast<float4*>(d_Weff + (size_t)n * D_IN);

    for (int g = threadIdx.x; g < D_IN / 4; g += blockDim.x) {
        const int4 c = crow[g];
        const float s = am[g >> 4];
        const int k0 = g * 4;
        float v[4] = {lut[c.x & 15] * s, lut[c.y & 15] * s,
                      lut[c.z & 15] * s, lut[c.w & 15] * s};
#pragma unroll
        for (int j = 0; j < 4; j++) {
            const float4* wa = reinterpret_cast<const float4*>(Wa + (size_t)(k0 + j) * RNK);
            float4 a0 = wa[0], a1 = wa[1], a2 = wa[2], a3 = wa[3];
            float l = a0.x * wb[0]  + a0.y * wb[1]  + a0.z * wb[2]  + a0.w * wb[3]
                    + a1.x * wb[4]  + a1.y * wb[5]  + a1.z * wb[6]  + a1.w * wb[7]
                    + a2.x * wb[8]  + a2.y * wb[9]  + a2.z * wb[10] + a2.w * wb[11]
                    + a3.x * wb[12] + a3.y * wb[13] + a3.z * wb[14] + a3.w * wb[15];
            v[j] += 2.0f * l;                   // SCALE = 2
        }
        orow[g] = make_float4(__uint_as_float(f2tf32(v[0])),
                              __uint_as_float(f2tf32(v[1])),
                              __uint_as_float(f2tf32(v[2])),
                              __uint_as_float(f2tf32(v[3])));
    }
}

// ---------------------------------------------------------------------------
__global__ __launch_bounds__(NTHREADS, 2)
void qgemm(const float* __restrict__ A, float* __restrict__ C) {
    extern __shared__ __align__(16) char smem[];
    const uint32_t sb = smem_u32(smem);

    const int tid  = threadIdx.x, lane = tid & 31, warp = tid >> 5;
    const int warpM = warp & 1;          // 2 slabs of 64 rows
    const int warpN = warp >> 1;         // 2 slabs of 64 cols
    const int gid = lane >> 2, tig = lane & 3;

    const int mBase = blockIdx.y * BM;
    const int nBase = blockIdx.x * BN;

    const float* Agp = A      + (size_t)mBase * D_IN;
    const float* Bgp = d_Weff + (size_t)nBase * D_IN;

    // ldmatrix lane->row/chunk components
    const int lm_m = lane >> 3, lm_j = lane & 7;
    const int aR = (lm_m & 1) * 8 + lm_j;       // row within 16-row block (A)
    const int aC = lm_m >> 1;                   // chunk offset 0/1 (A)
    const int bR = (lm_m >> 1) * 8 + lm_j;      // row within 16-row block (B)
    const int bC = lm_m & 1;                    // chunk offset 0/1 (B)

    // cp.async: per operand 128 rows x 8 chunks(16B) = 1024; 8 per thread
    auto load_stage = [&](int s, int kt) {
        const uint32_t As = sb + s * STAGE_BYTES;
        const uint32_t Bs = As + A_ST;
        const char* Ag = (const char*)Agp + (size_t)kt * 128;
        const char* Bg = (const char*)Bgp + (size_t)kt * 128;
#pragma unroll
        for (int h = 0; h < 8; h++) {
            const int idx = tid + h * 128;
            const int row = idx >> 3, ch = idx & 7;
            const uint32_t dst = row * 128 + ((ch ^ (row & 7)) << 4);
            cp_async16(As + dst, Ag + (size_t)row * (D_IN * 4) + (ch << 4));
        }
#pragma unroll
        for (int h = 0; h < 8; h++) {
            const int idx = tid + h * 128;
            const int row = idx >> 3, ch = idx & 7;
            const uint32_t dst = row * 128 + ((ch ^ (row & 7)) << 4);
            cp_async16(Bs + dst, Bg + (size_t)row * (D_IN * 4) + (ch << 4));
        }
    };

    float acc[4][8][4];
#pragma unroll
    for (int i = 0; i < 4; i++)
#pragma unroll
        for (int j = 0; j < 8; j++)
#pragma unroll
            for (int v = 0; v < 4; v++) acc[i][j][v] = 0.f;

    unsigned afr[2][4][4], bfr[2][8][2];

    auto frag_load = [&](int buf, uint32_t Ab, uint32_t Bb, int kk) {
        const int chunkBase = kk >> 2;          // kk in {0,8,16,24} -> 0,2,4,6
#pragma unroll
        for (int mi = 0; mi < 4; mi++) {
            uint32_t r0, r1, r2, r3;
            const int row = warpM * 64 + mi * 16 + aR;
            const int ch = (chunkBase + aC) ^ (row & 7);
            ldsm_x4(r0, r1, r2, r3, Ab + row * 128 + (ch << 4));
            afr[buf][mi][0] = f2tf32(__uint_as_float(r0));
            afr[buf][mi][1] = f2tf32(__uint_as_float(r1));
            afr[buf][mi][2] = f2tf32(__uint_as_float(r2));
            afr[buf][mi][3] = f2tf32(__uint_as_float(r3));
        }
#pragma unroll
        for (int np = 0; np < 4; np++) {
            uint32_t r0, r1, r2, r3;
            const int row = warpN * 64 + np * 16 + bR;
            const int ch = (chunkBase + bC) ^ (row & 7);
            ldsm_x4(r0, r1, r2, r3, Bb + row * 128 + (ch << 4));   // pre-rounded
            bfr[buf][2 * np][0] = r0;  bfr[buf][2 * np][1] = r1;
            bfr[buf][2 * np + 1][0] = r2;  bfr[buf][2 * np + 1][1] = r3;
        }
    };

    // prologue: stages 0,1 (tiles 0,1)
#pragma unroll
    for (int s = 0; s < STAGES - 1; s++) {
        load_stage(s, s);
        asm volatile("cp.async.commit_group;\n");
    }

    for (int kt = 0; kt < NT; kt++) {
        asm volatile("cp.async.wait_group 1;\n");   // tile kt arrived
        __syncthreads();                             // + all warps left slot kt-1

        // refill slot (kt+2)%3 == (kt-1)%3 with tile kt+2 (consumed at kt-1)
        if (kt + STAGES - 1 < NT)
            load_stage((kt + STAGES - 1) % STAGES, kt + STAGES - 1);
        asm volatile("cp.async.commit_group;\n");

        const int s = kt % STAGES;
        const uint32_t Ab = sb + s * STAGE_BYTES;
        const uint32_t Bb = Ab + A_ST;

        frag_load(0, Ab, Bb, 0);
#pragma unroll
        for (int ks = 0; ks < 4; ks++) {             // 4 k8-steps of BK=32
            const int cur = ks & 1;
            if (ks < 3) frag_load(cur ^ 1, Ab, Bb, (ks + 1) * 8);
#pragma unroll
            for (int mi = 0; mi < 4; mi++)
#pragma unroll
                for (int ni = 0; ni < 8; ni++)
                    mma_tf32(acc[mi][ni], afr[cur][mi], bfr[cur][ni]);
        }
    }

    // epilogue: float2 stores
#pragma unroll
    for (int mi = 0; mi < 4; mi++) {
        const int row0 = mBase + warpM * 64 + mi * 16 + gid;
#pragma unroll
        for (int ni = 0; ni < 8; ni++) {
            const int col = nBase + warpN * 64 + ni * 8 + tig * 2;
            *reinterpret_cast<float2*>(C + (size_t)row0 * D_OUT + col) =
                make_float2(acc[mi][ni][0], acc[mi][ni][1]);
            *reinterpret_cast<float2*>(C + (size_t)(row0 + 8) * D_OUT + col) =
                make_float2(acc[mi][ni][2], acc[mi][ni][3]);
        }
    }
}

// ---------------------------------------------------------------------------
extern "C" void kernel_launch(void* const* d_in, const int* in_sizes, int n_in,
                              void* d_out, int out_size) {
    const float* x      = (const float*)d_in[0];
    const int*   codes  = (const int*)  d_in[1];
    const float* absmax = (const float*)d_in[2];
    const float* Wa     = (const float*)d_in[3];
    const float* Wb     = (const float*)d_in[4];
    float* out = (float*)d_out;

    cudaFuncSetAttribute(qgemm, cudaFuncAttributeMaxDynamicSharedMemorySize, SMEM_DYN);

    build_weff_kernel<<<D_OUT, 256>>>((const int4*)codes, absmax, Wa, Wb);

    dim3 grid(D_OUT / BN, M_TOK / BM);   // (32, 64), n-fast for W_eff L2 reuse
    qgemm<<<grid, NTHREADS, SMEM_DYN>>>(x, out);
}